// round 16
// baseline (speedup 1.0000x reference)
#include <cuda_runtime.h>
#include <cuda_fp16.h>
#include <cstdint>
#include <math.h>

#define NPTS 100000
#define CDIM 96
#define GRES 32
#define G3   (GRES*GRES*GRES)
#define PAD  34
#define PP2  (PAD*PAD)
#define PGV  (PP2*PAD)

// ======================= scratch (device globals) ===========================
__device__ int   g_vidx[NPTS];
__device__ int   g_icnt[G3];
__device__ int   g_start[G3+1];
__device__ int   g_pos[G3];
__device__ int   g_sorted[NPTS];
__device__ int   g_nbi[8*NPTS];       // indexed by SORTED slot
__device__ float g_nbw[8*NPTS];       // indexed by SORTED slot
__device__ float g_P[27*G3];          // per-tap dot products (attn stage)
__device__ __half g_conv [G3*CDIM];   // conv outputs in fp16
__device__ __half g_conv2[G3*CDIM];
__device__ float g_vout[G3];
__device__ float g_q[NPTS*CDIM];
__device__ float g_h[NPTS*CDIM];
__device__ float g_energy[NPTS*CDIM];
__device__ float g_attn[NPTS];
// padded fp16 grids (all hi-only; 1-term A everywhere)
__device__ __half g_pA96_hi [PGV*128];   // voxelized query input
__device__ __half g_pB96_hi [PGV*128];   // voxelized hidden input
__device__ __half g_pA192_hi[PGV*192];
// cached voxelized q_out (interior), reused stage3 -> stage5
__device__ __half g_pQ96_hi[PGV*96];
// pre-swizzled fp16 conv weights: [tap*nch+chunk][6144 = 96 rows x 64 ci]
__device__ __half g_wqB [27*2*6144];
__device__ __half g_whB [27*2*6144];
__device__ __half g_attB[27*3*6144];
__device__ __half g_updB[27*3*6144];
// pre-swizzled fp16 linear weights: [chunk][6144]
__device__ __half g_wqlB [2*6144];
__device__ __half g_whlB [2*6144];
__device__ __half g_attlB[3*6144];
__device__ __half g_updlB[3*6144];
__device__ float g_vT[27*CDIM];

// ======================= mma/ldmatrix/cp.async helpers =======================
__device__ __forceinline__ uint32_t smem_u32(const void* p) {
    uint32_t a;
    asm("{ .reg .u64 t; cvta.to.shared.u64 t, %1; cvt.u32.u64 %0, t; }" : "=r"(a) : "l"(p));
    return a;
}
__device__ __forceinline__ void ldsm4(uint32_t* r, uint32_t addr) {
    asm volatile("ldmatrix.sync.aligned.m8n8.x4.shared.b16 {%0,%1,%2,%3}, [%4];"
        : "=r"(r[0]), "=r"(r[1]), "=r"(r[2]), "=r"(r[3]) : "r"(addr));
}
__device__ __forceinline__ void mma16816h(float* c, const uint32_t* a, const uint32_t* b) {
    asm volatile("mma.sync.aligned.m16n8k16.row.col.f32.f16.f16.f32 "
        "{%0,%1,%2,%3}, {%4,%5,%6,%7}, {%8,%9}, {%0,%1,%2,%3};"
        : "+f"(c[0]), "+f"(c[1]), "+f"(c[2]), "+f"(c[3])
        : "r"(a[0]), "r"(a[1]), "r"(a[2]), "r"(a[3]), "r"(b[0]), "r"(b[1]));
}
__device__ __forceinline__ void cpa16(uint32_t dst, const void* src) {
    asm volatile("cp.async.cg.shared.global [%0], [%1], 16;" :: "r"(dst), "l"(src));
}
__device__ __forceinline__ void cpa_commit() { asm volatile("cp.async.commit_group;"); }
__device__ __forceinline__ void cpa_wait0()  { asm volatile("cp.async.wait_group 0;"); }
__device__ __forceinline__ void cpa_wait1()  { asm volatile("cp.async.wait_group 1;"); }
__device__ __forceinline__ void cpa_wait2()  { asm volatile("cp.async.wait_group 2;"); }

// ======================= sort/index kernels ==================================
__global__ void zeroi_k(int* __restrict__ p, int n) {
    int i = blockIdx.x * blockDim.x + threadIdx.x;
    if (i < n) p[i] = 0;
}

__global__ void vox_k(const float* __restrict__ coords) {
    int p = blockIdx.x * blockDim.x + threadIdx.x;
    if (p >= NPTS) return;
    int vx = min(max((int)floorf(coords[3*p+0]), 0), GRES-1);
    int vy = min(max((int)floorf(coords[3*p+1]), 0), GRES-1);
    int vz = min(max((int)floorf(coords[3*p+2]), 0), GRES-1);
    int flat = (vx*GRES + vy)*GRES + vz;
    g_vidx[p] = flat;
    atomicAdd(&g_icnt[flat], 1);
}

__global__ void __launch_bounds__(1024) scan_k() {
    __shared__ int bs[1024];
    int t = threadIdx.x;
    int base = t * 32;
    int loc[32];
    int s = 0;
    #pragma unroll
    for (int k = 0; k < 32; k++) { loc[k] = s; s += g_icnt[base + k]; }
    bs[t] = s;
    __syncthreads();
    #pragma unroll
    for (int d = 1; d < 1024; d <<= 1) {
        int v = (t >= d) ? bs[t - d] : 0;
        __syncthreads();
        bs[t] += v;
        __syncthreads();
    }
    int off = bs[t] - s;
    #pragma unroll
    for (int k = 0; k < 32; k++) {
        g_start[base + k] = off + loc[k];
        g_pos[base + k]   = off + loc[k];
    }
    if (t == 1023) g_start[G3] = off + s;
}

// fused counting-sort fill + trilinear neighbor precompute (sorted-slot order)
__global__ void filltrilin_k(const float* __restrict__ coords) {
    int p = blockIdx.x * blockDim.x + threadIdx.x;
    if (p >= NPTS) return;
    int s = atomicAdd(&g_pos[g_vidx[p]], 1);
    g_sorted[s] = p;
    float cx = coords[3*p+0], cy = coords[3*p+1], cz = coords[3*p+2];
    float bx = floorf(cx), by = floorf(cy), bz = floorf(cz);
    float fx = cx - bx, fy = cy - by, fz = cz - bz;
    int ix = (int)bx, iy = (int)by, iz = (int)bz;
    #pragma unroll
    for (int j = 0; j < 8; j++) {
        int dx = (j >> 2) & 1, dy = (j >> 1) & 1, dz = j & 1;
        int nx = ix + dx, ny = iy + dy, nz = iz + dz;
        bool valid = (nx >= 0 && nx < GRES && ny >= 0 && ny < GRES && nz >= 0 && nz < GRES);
        int cxc = min(max(nx,0),GRES-1), cyc = min(max(ny,0),GRES-1), czc = min(max(nz,0),GRES-1);
        int flc = (cxc*GRES + cyc)*GRES + czc;
        float w = (dx ? fx : 1.f-fx) * (dy ? fy : 1.f-fy) * (dz ? fz : 1.f-fz);
        if (!valid || g_icnt[flc] == 0) w = 0.f;
        g_nbi[j*NPTS + s] = flc;
        g_nbw[j*NPTS + s] = w;
    }
}

// ======================= fp16 helpers ========================================
__device__ __forceinline__ void f16_store4(float4 acc, __half* dhi, size_t o) {
    __half2 hA = __floats2half2_rn(acc.x, acc.y);
    __half2 hB = __floats2half2_rn(acc.z, acc.w);
    *(__half2*)(dhi + o)     = hA;
    *(__half2*)(dhi + o + 2) = hB;
}

// merged q+h INPUT voxelize (hi only)
__global__ void gathervox_qh_k(const float* __restrict__ q, const float* __restrict__ h) {
    int i = blockIdx.x * blockDim.x + threadIdx.x;
    if (i >= 2 * G3 * 24) return;
    bool sec = (i >= G3 * 24);
    int j = sec ? i - G3 * 24 : i;
    int c4 = j % 24;
    int v  = j / 24;
    int vx = v >> 10, vy = (v >> 5) & 31, vz = v & 31;
    int pv = ((vx + 1) * PAD + (vy + 1)) * PAD + (vz + 1);
    int ci = c4 * 4;
    const float* src = sec ? h : q;

    float4 acc = make_float4(0.f, 0.f, 0.f, 0.f);
    int s0 = g_start[v], s1 = g_start[v+1];
    if (s1 > s0) {
        for (int k = s0; k < s1; k++) {
            int pid = g_sorted[k];
            float4 f = *(const float4*)(src + (size_t)pid * 96 + ci);
            acc.x += f.x; acc.y += f.y; acc.z += f.z; acc.w += f.w;
        }
        float invn = 1.f / (float)(s1 - s0);
        acc.x *= invn; acc.y *= invn; acc.z *= invn; acc.w *= invn;
    }
    f16_store4(acc, sec ? g_pB96_hi : g_pA96_hi, (size_t)pv * 128 + ci);
}

// stage-3 voxelize of OUTPUTS: pA192 = [mean(h_out) | mean(q_out)] + cache q grid
__global__ void gathervox192_k(const float* __restrict__ h, const float* __restrict__ q) {
    int i = blockIdx.x * blockDim.x + threadIdx.x;
    if (i >= 2 * G3 * 24) return;
    bool sec = (i >= G3 * 24);   // sec = q half
    int j = sec ? i - G3 * 24 : i;
    int c4 = j % 24;
    int v  = j / 24;
    int vx = v >> 10, vy = (v >> 5) & 31, vz = v & 31;
    int pv = ((vx + 1) * PAD + (vy + 1)) * PAD + (vz + 1);
    int ci = c4 * 4;
    const float* src = sec ? q : h;

    float4 acc = make_float4(0.f, 0.f, 0.f, 0.f);
    int s0 = g_start[v], s1 = g_start[v+1];
    if (s1 > s0) {
        for (int k = s0; k < s1; k++) {
            int pid = g_sorted[k];
            float4 f = *(const float4*)(src + (size_t)pid * 96 + ci);
            acc.x += f.x; acc.y += f.y; acc.z += f.z; acc.w += f.w;
        }
        float invn = 1.f / (float)(s1 - s0);
        acc.x *= invn; acc.y *= invn; acc.z *= invn; acc.w *= invn;
    }
    if (!sec) {
        f16_store4(acc, g_pA192_hi, (size_t)pv * 192 + ci);
    } else {
        f16_store4(acc, g_pA192_hi, (size_t)pv * 192 + 96 + ci);
        f16_store4(acc, g_pQ96_hi, (size_t)pv * 96 + ci);
    }
}

// stage-5: merged (q-cache copy) + (mean(attn*h) gather)
__global__ void mkq_sc_k(const float* __restrict__ h, const float* __restrict__ scale) {
    const int NCOPY = G3 * 12;
    int i = blockIdx.x * blockDim.x + threadIdx.x;
    if (i < NCOPY) {
        int u = i % 12;
        int v = i / 12;
        int vx = v >> 10, vy = (v >> 5) & 31, vz = v & 31;
        int pv = ((vx + 1) * PAD + (vy + 1)) * PAD + (vz + 1);
        size_t s = (size_t)pv * 96 + u * 8;
        size_t d = (size_t)pv * 192 + u * 8;
        *(uint4*)(g_pA192_hi + d) = *(const uint4*)(g_pQ96_hi + s);
        return;
    }
    int j = i - NCOPY;
    if (j >= G3 * 24) return;
    int c4 = j % 24;
    int v  = j / 24;
    int vx = v >> 10, vy = (v >> 5) & 31, vz = v & 31;
    int pv = ((vx + 1) * PAD + (vy + 1)) * PAD + (vz + 1);
    int ci = c4 * 4;
    float4 acc = make_float4(0.f, 0.f, 0.f, 0.f);
    int s0 = g_start[v], s1 = g_start[v+1];
    if (s1 > s0) {
        for (int k = s0; k < s1; k++) {
            int pid = g_sorted[k];
            float4 f = *(const float4*)(h + (size_t)pid * 96 + ci);
            float m = scale[pid];
            acc.x += f.x * m; acc.y += f.y * m; acc.z += f.z * m; acc.w += f.w * m;
        }
        float invn = 1.f / (float)(s1 - s0);
        acc.x *= invn; acc.y *= invn; acc.z *= invn; acc.w *= invn;
    }
    f16_store4(acc, g_pA192_hi, (size_t)pv * 192 + 96 + ci);
}

// ======================= merged weight prep + grid zero ======================
__device__ __forceinline__ void conv_prep(int i, const float* w, __half* dst,
                                          int CIN, int KPAD, int NCH) {
    int co  = i % 96;
    int r   = i / 96;
    int ci  = r % KPAD;
    int tap = r / KPAD;
    float val = (ci < CIN) ? w[((size_t)co * CIN + ci) * 27 + tap] : 0.f;
    int chunk = ci >> 6;
    int cw = ci & 63;
    uint32_t elem = (uint32_t)co * 64 + (uint32_t)(((cw >> 3) ^ (co & 7)) * 8) + (cw & 7);
    dst[(size_t)(tap * NCH + chunk) * 6144 + elem] = __float2half_rn(val);
}
__device__ __forceinline__ void lin_prep(int i, const float* w, __half* dst, int CIN) {
    int co = i % 96;
    int ci = i / 96;
    float val = (ci < CIN) ? w[(size_t)co * CIN + ci] : 0.f;
    int chunk = ci >> 6;
    int cw = ci & 63;
    uint32_t elem = (uint32_t)co * 64 + (uint32_t)(((cw >> 3) ^ (co & 7)) * 8) + (cw & 7);
    dst[(size_t)chunk * 6144 + elem] = __float2half_rn(val);
}

#define U128 (PGV * 128 / 8)
#define U192 (PGV * 192 / 8)

__global__ void prep_all_k(const float* wq, const float* wh, const float* att,
                           const float* upd, const float* wql, const float* whl,
                           const float* attl, const float* updl, const float* vconv,
                           __half* dwq, __half* dwh, __half* datt, __half* dupd,
                           __half* dwql, __half* dwhl, __half* dattl, __half* dupdl,
                           __half* za, __half* zb, __half* ze) {
    const int C96 = 27*128*96, C192 = 27*192*96, L96 = 128*96, L192 = 192*96;
    long long i = (long long)blockIdx.x * blockDim.x + threadIdx.x;
    uint4 z = make_uint4(0u, 0u, 0u, 0u);
    if (i < U128)            { ((uint4*)za)[i] = z; return; }
    i -= U128;
    if (i < U128)            { ((uint4*)zb)[i] = z; return; }
    i -= U128;
    if (i < U192)            { ((uint4*)ze)[i] = z; return; }
    i -= U192;
    int k = (int)i;
    if (k < C96) { conv_prep(k, wq, dwq, 96, 128, 2); return; }
    k -= C96;
    if (k < C96) { conv_prep(k, wh, dwh, 96, 128, 2); return; }
    k -= C96;
    if (k < C192) { conv_prep(k, att, datt, 192, 192, 3); return; }
    k -= C192;
    if (k < C192) { conv_prep(k, upd, dupd, 192, 192, 3); return; }
    k -= C192;
    if (k < L96) { lin_prep(k, wql, dwql, 96); return; }
    k -= L96;
    if (k < L96) { lin_prep(k, whl, dwhl, 96); return; }
    k -= L96;
    if (k < L192) { lin_prep(k, attl, dattl, 192); return; }
    k -= L192;
    if (k < L192) { lin_prep(k, updl, dupdl, 192); return; }
    k -= L192;
    if (k < 27*96) { int t = k % 27, ci = k / 27; g_vT[t*96 + ci] = vconv[ci*27 + t]; }
}

// ======================= HMMA 3x3x3 conv (pipelined A/B, dual-job) ===========
// A double-buffered across (cc,dx) iterations; B triple-buffered, prefetch
// depth 2. Next iteration's A slab issued at tap 2 (own group, after B[g+4]);
// forced complete at tap 5's wait — covered by ~3 taps of compute.
#define CV_ABUF 26112            // A slab buffer: 204 rows * 128B
#define CV_B0   52224
#define CV_BBUF 12288
#define SM_TOT  89088

template<int KPAD, int NCH>
__global__ void __launch_bounds__(256, 2) conv_mma_k(
    const __half* __restrict__ wBa, const __half* __restrict__ pAhiA,
    __half* __restrict__ outA,
    const __half* __restrict__ wBb, const __half* __restrict__ pAhiB,
    __half* __restrict__ outB,
    int split_blk) {
    extern __shared__ char smem[];
    uint32_t sb = smem_u32(smem);
    int tid = threadIdx.x;
    int warp = tid >> 5, lane = tid & 31;
    int m_off = (warp & 3) * 32;
    int n_off = (warp >> 2) * 48;

    int blk = blockIdx.x;
    bool sec = (blk >= split_blk);
    if (sec) blk -= split_blk;
    const __half* wB   = sec ? wBb   : wBa;
    const __half* pAhi = sec ? pAhiB : pAhiA;
    __half* outp = sec ? outB : outA;

    int x  = blk >> 3;
    int y0 = (blk & 7) * 4;

    float acc[2][6][4];
    #pragma unroll
    for (int mi = 0; mi < 2; mi++)
        #pragma unroll
        for (int nj = 0; nj < 6; nj++)
            #pragma unroll
            for (int e = 0; e < 4; e++) acc[mi][nj][e] = 0.f;

    int a_row_in = (lane & 7) + ((lane >> 3) & 1) * 8;
    int a_khalf  = lane >> 4;
    int b_row_in = (lane & 7) + ((lane >> 3) >> 1) * 8;
    int b_khalf  = (lane >> 3) & 1;

    int rb[2];
    #pragma unroll
    for (int mi = 0; mi < 2; mi++) {
        int m = m_off + mi * 16 + a_row_in;
        rb[mi] = (m >> 5) * 34 + (m & 31);
    }
    int brow[3];
    #pragma unroll
    for (int ni = 0; ni < 3; ni++) brow[ni] = n_off + ni * 16 + b_row_in;

    const int NITER = NCH * 3;
    const int TOT = NITER * 9;

    // B weight tile source offset for global tap g
    auto b_src = [&](int g) -> const __half* {
        int itg = g / 9, t9 = g % 9;
        int cc = itg / 3, dx = itg % 3;
        return wB + (size_t)((dx * 9 + t9) * NCH + cc) * 6144;
    };
    auto issue_B = [&](int g) {
        const __half* bs = b_src(g);
        uint32_t dst = sb + CV_B0 + (uint32_t)(g % 3) * CV_BBUF;
        #pragma unroll
        for (int t = tid; t < 768; t += 256)
            cpa16(dst + t * 16, bs + t * 8);
    };
    auto issue_A = [&](int itg) {
        int cc = itg / 3, dx = itg % 3;
        bool sk = (KPAD == 128 && cc == 1);
        int c8max = sk ? 4 : 8;
        int c8sh  = sk ? 2 : 3;
        int ahalf = 204 * c8max;
        uint32_t dst = sb + (uint32_t)(itg & 1) * CV_ABUF;
        size_t pvbase = ((size_t)(x + dx) * PAD + y0) * PAD;
        for (int t = tid; t < ahalf; t += 256) {
            int r = t >> c8sh, c8 = t & (c8max - 1);
            const __half* src = pAhi + (pvbase + r) * KPAD + cc * 64 + c8 * 8;
            cpa16(dst + (uint32_t)r * 128 + ((c8 ^ (r & 7)) << 4), src);
        }
    };

    // prologue: group0 = {A[0], B[0]}, group1 = {B[1]}
    issue_A(0);
    issue_B(0);
    cpa_commit();
    issue_B(1);
    cpa_commit();

    for (int it = 0; it < NITER; it++) {
        int cc = it / 3;
        bool shortk = (KPAD == 128 && cc == 1);
        int kmax = shortk ? 2 : 4;
        uint32_t abase = sb + (uint32_t)(it & 1) * CV_ABUF;
        bool hasA = (it + 1 < NITER);     // A-group in flight this iteration

        for (int t9 = 0; t9 < 9; t9++) {
            int g = it * 9 + t9;
            // wait: need B[g] (and A[it], already forced earlier).
            if (hasA && (t9 == 3 || t9 == 4)) cpa_wait2();
            else cpa_wait1();
            __syncthreads();
            // prefetch B two taps ahead
            if (g + 2 < TOT) { issue_B(g + 2); cpa_commit(); }
            // next iteration's A slab (own group, after this tap's B group)
            if (t9 == 2 && hasA) { issue_A(it + 1); cpa_commit(); }

            uint32_t bbase = sb + CV_B0 + (uint32_t)(g % 3) * CV_BBUF;
            int toff = (t9 / 3) * PAD + (t9 % 3);

            #pragma unroll 4
            for (int kk = 0; kk < kmax; kk++) {
                uint32_t ah[2][4], bh[3][4];
                #pragma unroll
                for (int mi = 0; mi < 2; mi++) {
                    int r = rb[mi] + toff;
                    int kc = kk * 2 + a_khalf;
                    uint32_t off = (uint32_t)r * 128 + (uint32_t)((kc ^ (r & 7)) << 4);
                    ldsm4(ah[mi], abase + off);
                }
                #pragma unroll
                for (int ni = 0; ni < 3; ni++) {
                    int r = brow[ni];
                    int kc = kk * 2 + b_khalf;
                    uint32_t off = (uint32_t)r * 128 + (uint32_t)((kc ^ (r & 7)) << 4);
                    ldsm4(bh[ni], bbase + off);
                }
                #pragma unroll
                for (int mi = 0; mi < 2; mi++) {
                    #pragma unroll
                    for (int nj = 0; nj < 6; nj++) {
                        const uint32_t* bfh = &bh[nj >> 1][(nj & 1) * 2];
                        mma16816h(acc[mi][nj], ah[mi], bfh);
                    }
                }
            }
        }
    }

    #pragma unroll
    for (int mi = 0; mi < 2; mi++) {
        #pragma unroll
        for (int half = 0; half < 2; half++) {
            int r = m_off + mi * 16 + (lane >> 2) + half * 8;
            int j = r >> 5, z = r & 31;
            size_t vbase = ((size_t)(x * GRES + y0 + j) * GRES + z) * 96;
            #pragma unroll
            for (int nj = 0; nj < 6; nj++) {
                int co = n_off + nj * 8 + 2 * (lane & 3);
                __half2 hv = __floats2half2_rn(acc[mi][nj][half * 2],
                                               acc[mi][nj][half * 2 + 1]);
                *(__half2*)(&outp[vbase + co]) = hv;
            }
        }
    }
}

// ======================= fused linear GEMM + devox epilogue (dual, SORTED) ===
#define L_B0  16384              // A: 128 rows * 128B
#define L_B1  28672
#define L_TOT 40960

template<int KPAD, int NCH>
__global__ void __launch_bounds__(256, 2) lindevox_k(
    const float* __restrict__ x1a, const float* __restrict__ x2a,
    const float* __restrict__ s2a, const __half* __restrict__ wBa,
    const float* __restrict__ biasa, const __half* __restrict__ convA,
    float* __restrict__ outa,
    const float* __restrict__ x1b, const float* __restrict__ x2b,
    const float* __restrict__ s2b, const __half* __restrict__ wBb,
    const float* __restrict__ biasb, const __half* __restrict__ convB,
    float* __restrict__ outb,
    int split_blk, int do_tanh) {
    extern __shared__ char smem[];
    uint32_t sb = smem_u32(smem);
    int tid = threadIdx.x;
    int warp = tid >> 5, lane = tid & 31;
    int m_off = (warp & 3) * 32;
    int n_off = (warp >> 2) * 48;

    int blk = blockIdx.x;
    bool sec = (blk >= split_blk);
    if (sec) blk -= split_blk;
    const float* x1 = sec ? x1b : x1a;
    const float* x2 = sec ? x2b : x2a;
    const float* scale2 = sec ? s2b : s2a;
    const __half* wB = sec ? wBb : wBa;
    const float* bias = sec ? biasb : biasa;
    const __half* convsrc = sec ? convB : convA;
    float* out = sec ? outb : outa;
    int pbase = blk * 128;           // SORTED slot base

    float acc[2][6][4];
    #pragma unroll
    for (int mi = 0; mi < 2; mi++)
        #pragma unroll
        for (int nj = 0; nj < 6; nj++)
            #pragma unroll
            for (int e = 0; e < 4; e++) acc[mi][nj][e] = 0.f;

    int a_row_in = (lane & 7) + ((lane >> 3) & 1) * 8;
    int a_khalf  = lane >> 4;
    int b_row_in = (lane & 7) + ((lane >> 3) >> 1) * 8;
    int b_khalf  = (lane >> 3) & 1;
    int brow[3];
    #pragma unroll
    for (int ni = 0; ni < 3; ni++) brow[ni] = n_off + ni * 16 + b_row_in;

    #pragma unroll
    for (int t = tid; t < 768; t += 256)
        cpa16(sb + L_B0 + t * 16, wB + t * 8);
    cpa_commit();

    for (int ch = 0; ch < NCH; ch++) {
        if (ch) __syncthreads();
        bool shortk = (KPAD == 128 && ch == 1);
        int kmax  = shortk ? 2 : 4;
        int c8max = shortk ? 4 : 8;
        int c8sh  = shortk ? 2 : 3;

        for (int gidx = tid; gidx < 128 * c8max; gidx += 256) {
            int r = gidx >> c8sh, c8 = gidx & (c8max - 1);
            int slot = pbase + r;
            int colbase = ch * 64 + c8 * 8;
            float v[8];
            bool have = (slot < NPTS) && (colbase < ((KPAD == 128) ? 96 : 192));
            if (have) {
                int p = g_sorted[slot];
                const float* srcp;
                float m = 1.f;
                if (colbase < 96) srcp = x1 + (size_t)p * 96 + colbase;
                else {
                    srcp = x2 + (size_t)p * 96 + (colbase - 96);
                    if (scale2) m = scale2[p];
                }
                float4 aa = *(const float4*)srcp;
                float4 bb = *(const float4*)(srcp + 4);
                v[0]=aa.x*m; v[1]=aa.y*m; v[2]=aa.z*m; v[3]=aa.w*m;
                v[4]=bb.x*m; v[5]=bb.y*m; v[6]=bb.z*m; v[7]=bb.w*m;
            } else {
                #pragma unroll
                for (int e = 0; e < 8; e++) v[e] = 0.f;
            }
            uint4 hv;
            uint32_t* hp = (uint32_t*)&hv;
            #pragma unroll
            for (int e = 0; e < 4; e++) {
                __half2 hh = __floats2half2_rn(v[2*e], v[2*e+1]);
                hp[e] = *(uint32_t*)&hh;
            }
            uint32_t addr = (uint32_t)r * 128 + (uint32_t)((c8 ^ (r & 7)) << 4);
            *(uint4*)(smem + addr) = hv;
        }
        if (ch + 1 < NCH) {
            const __half* bs = wB + (size_t)(ch + 1) * 6144;
            uint32_t dst = sb + ((ch & 1) ? L_B0 : L_B1);
            #pragma unroll
            for (int t = tid; t < 768; t += 256)
                cpa16(dst + t * 16, bs + t * 8);
            cpa_commit();
            cpa_wait1();
        } else {
            cpa_wait0();
        }
        __syncthreads();

        uint32_t bbase = sb + ((ch & 1) ? L_B1 : L_B0);
        #pragma unroll 4
        for (int kk = 0; kk < kmax; kk++) {
            uint32_t ah[2][4], bh[3][4];
            #pragma unroll
            for (int mi = 0; mi < 2; mi++) {
                int r = m_off + mi * 16 + a_row_in;
                int kc = kk * 2 + a_khalf;
                uint32_t off = (uint32_t)r * 128 + (uint32_t)((kc ^ (r & 7)) << 4);
                ldsm4(ah[mi], sb + off);
            }
            #pragma unroll
            for (int ni = 0; ni < 3; ni++) {
                int r = brow[ni];
                int kc = kk * 2 + b_khalf;
                uint32_t off = (uint32_t)r * 128 + (uint32_t)((kc ^ (r & 7)) << 4);
                ldsm4(bh[ni], bbase + off);
            }
            #pragma unroll
            for (int mi = 0; mi < 2; mi++) {
                #pragma unroll
                for (int nj = 0; nj < 6; nj++) {
                    const uint32_t* bfh = &bh[nj >> 1][(nj & 1) * 2];
                    mma16816h(acc[mi][nj], ah[mi], bfh);
                }
            }
        }
    }

    // ---- epilogue: devox gather (fp16 conv, sorted slots) + bias + tanh ----
    #pragma unroll
    for (int mi = 0; mi < 2; mi++) {
        #pragma unroll
        for (int half = 0; half < 2; half++) {
            int r = m_off + mi * 16 + (lane >> 2) + half * 8;
            int slot = pbase + r;
            if (slot >= NPTS) continue;
            int p = g_sorted[slot];
            #pragma unroll
            for (int j = 0; j < 8; j++) {
                float w = g_nbw[j*NPTS + slot];
                if (w != 0.f) {
                    const __half* gp = convsrc + (size_t)g_nbi[j*NPTS + slot] * 96;
                    #pragma unroll
                    for (int nj = 0; nj < 6; nj++) {
                        int co = n_off + nj * 8 + 2 * (lane & 3);
                        float2 gg = __half22float2(*(const __half2*)(gp + co));
                        acc[mi][nj][half*2]   += w * gg.x;
                        acc[mi][nj][half*2+1] += w * gg.y;
                    }
                }
            }
            #pragma unroll
            for (int nj = 0; nj < 6; nj++) {
                int co = n_off + nj * 8 + 2 * (lane & 3);
                float2 bb = *(const float2*)(bias + co);
                float vx = acc[mi][nj][half*2]   + bb.x;
                float vy = acc[mi][nj][half*2+1] + bb.y;
                if (do_tanh) { vx = tanhf(vx); vy = tanhf(vy); }
                *(float2*)(out + (size_t)p * 96 + co) = make_float2(vx, vy);
            }
        }
    }
}

// ======================= attn stage ==========================================
__global__ void __launch_bounds__(256) voxdot_k(const float* __restrict__ src) {
    __shared__ float ws[27*96];
    int tid = threadIdx.x;
    for (int i = tid; i < 27*96; i += 256) ws[i] = g_vT[i];
    __syncthreads();
    int wid = tid >> 5, lane = tid & 31;
    int v = blockIdx.x * 8 + wid;
    if (v >= G3) return;
    int s0 = g_start[v], s1 = g_start[v+1];
    float a0 = 0.f, a1 = 0.f, a2 = 0.f;
    for (int k = s0; k < s1; k++) {
        const float* r = src + (size_t)g_sorted[k] * 96;
        a0 += r[lane]; a1 += r[lane+32]; a2 += r[lane+64];
    }
    if (s1 > s0) {
        float invn = 1.f / (float)(s1 - s0);
        a0 *= invn; a1 *= invn; a2 *= invn;
    }
    #pragma unroll 9
    for (int t = 0; t < 27; t++) {
        float s = a0*ws[t*96+lane] + a1*ws[t*96+lane+32] + a2*ws[t*96+lane+64];
        s += __shfl_xor_sync(0xFFFFFFFF, s, 16);
        s += __shfl_xor_sync(0xFFFFFFFF, s, 8);
        s += __shfl_xor_sync(0xFFFFFFFF, s, 4);
        s += __shfl_xor_sync(0xFFFFFFFF, s, 2);
        s += __shfl_xor_sync(0xFFFFFFFF, s, 1);
        if (lane == 0) g_P[t*G3 + v] = s;
    }
}

__global__ void stencil_k() {
    int v = blockIdx.x * blockDim.x + threadIdx.x;
    if (v >= G3) return;
    int px = v >> 10, py = (v >> 5) & 31, pz = v & 31;
    float acc = 0.f;
    #pragma unroll
    for (int t = 0; t < 27; t++) {
        int kx = t / 9, ky = (t / 3) % 3, kz = t % 3;
        int nx = px + kx - 1, ny = py + ky - 1, nz = pz + kz - 1;
        if ((unsigned)nx < GRES && (unsigned)ny < GRES && (unsigned)nz < GRES)
            acc += g_P[t*G3 + ((nx<<5) + ny)*32 + nz];
    }
    g_vout[v] = acc;
}

__global__ void attn_k(const float* __restrict__ energy,
                       const float* __restrict__ v_lw, const float* __restrict__ v_lb) {
    int s = blockIdx.x * blockDim.x + threadIdx.x;
    if (s >= NPTS) return;
    int p = g_sorted[s];
    float acc = v_lb[0];
    #pragma unroll
    for (int j = 0; j < 8; j++) {
        float w = g_nbw[j*NPTS + s];
        if (w != 0.f) acc += w * g_vout[g_nbi[j*NPTS + s]];
    }
    const float4* er4 = (const float4*)(energy + (size_t)p * CDIM);
    const float4* vw4 = (const float4*)v_lw;
    #pragma unroll 6
    for (int cb = 0; cb < 24; cb++) {
        float4 e = er4[cb], w = vw4[cb];
        acc += e.x*w.x + e.y*w.y + e.z*w.z + e.w*w.w;
    }
    g_attn[p] = acc;
}

// ======================= host orchestration =================================
extern "C" void kernel_launch(void* const* d_in, const int* in_sizes, int n_in,
                              void* d_out, int out_size) {
    const float* hidden   = (const float*)d_in[0];
    const float* query    = (const float*)d_in[1];
    const float* coords   = (const float*)d_in[2];
    const float* wq_conv  = (const float*)d_in[3];
    const float* wq_lw    = (const float*)d_in[4];
    const float* wq_lb    = (const float*)d_in[5];
    const float* wh_conv  = (const float*)d_in[6];
    const float* wh_lw    = (const float*)d_in[7];
    const float* wh_lb    = (const float*)d_in[8];
    const float* att_conv = (const float*)d_in[9];
    const float* att_lw   = (const float*)d_in[10];
    const float* att_lb   = (const float*)d_in[11];
    const float* v_conv   = (const float*)d_in[12];
    const float* v_lw     = (const float*)d_in[13];
    const float* v_lb     = (const float*)d_in[14];
    const float* upd_conv = (const float*)d_in[15];
    const float* upd_lw   = (const float*)d_in[16];
    const float* upd_lb   = (const float*)d_in[17];
    float* out = (float*)d_out;

    int *picnt;
    float *pq, *ph, *pe, *pattn;
    __half *pconv, *pconv2;
    __half *pwqB, *pwhB, *pattB, *pupdB;
    __half *pwqlB, *pwhlB, *pattlB, *pupdlB;
    __half *pA96h, *pB96h, *pA192h;
    cudaGetSymbolAddress((void**)&picnt,  g_icnt);
    cudaGetSymbolAddress((void**)&pq,     g_q);
    cudaGetSymbolAddress((void**)&ph,     g_h);
    cudaGetSymbolAddress((void**)&pe,     g_energy);
    cudaGetSymbolAddress((void**)&pattn,  g_attn);
    cudaGetSymbolAddress((void**)&pconv,  g_conv);
    cudaGetSymbolAddress((void**)&pconv2, g_conv2);
    cudaGetSymbolAddress((void**)&pwqB,   g_wqB);
    cudaGetSymbolAddress((void**)&pwhB,   g_whB);
    cudaGetSymbolAddress((void**)&pattB,  g_attB);
    cudaGetSymbolAddress((void**)&pupdB,  g_updB);
    cudaGetSymbolAddress((void**)&pwqlB,  g_wqlB);
    cudaGetSymbolAddress((void**)&pwhlB,  g_whlB);
    cudaGetSymbolAddress((void**)&pattlB, g_attlB);
    cudaGetSymbolAddress((void**)&pupdlB, g_updlB);
    cudaGetSymbolAddress((void**)&pA96h,  g_pA96_hi);
    cudaGetSymbolAddress((void**)&pB96h,  g_pB96_hi);
    cudaGetSymbolAddress((void**)&pA192h, g_pA192_hi);

    cudaFuncSetAttribute(conv_mma_k<128,2>, cudaFuncAttributeMaxDynamicSharedMemorySize, SM_TOT);
    cudaFuncSetAttribute(conv_mma_k<192,3>, cudaFuncAttributeMaxDynamicSharedMemorySize, SM_TOT);
    cudaFuncSetAttribute(lindevox_k<128,2>, cudaFuncAttributeMaxDynamicSharedMemorySize, L_TOT);
    cudaFuncSetAttribute(lindevox_k<192,3>, cudaFuncAttributeMaxDynamicSharedMemorySize, L_TOT);

    const int TB = 256;
    auto gs = [](long long n, int tb){ return (int)((n + tb - 1) / tb); };
    const int LBLK = (NPTS + 127) / 128;   // 782
    const long long ZN = 2LL*U128 + 1LL*U192;
    const long long PREP_N = ZN + 2LL*27*128*96 + 2LL*27*192*96
                           + 2LL*128*96 + 2LL*192*96 + 27*96;

    // --- shared precompute ---
    zeroi_k<<<gs(G3,TB), TB>>>(picnt, G3);
    vox_k<<<gs(NPTS,TB), TB>>>(coords);
    scan_k<<<1, 1024>>>();
    filltrilin_k<<<gs(NPTS,TB), TB>>>(coords);
    prep_all_k<<<gs(PREP_N,TB), TB>>>(wq_conv, wh_conv, att_conv, upd_conv,
                                      wq_lw, wh_lw, att_lw, upd_lw, v_conv,
                                      pwqB, pwhB, pattB, pupdB,
                                      pwqlB, pwhlB, pattlB, pupdlB,
                                      pA96h, pB96h, pA192h);

    // --- merged sconv q + sconv h ---
    gathervox_qh_k<<<gs(2LL*G3*24,TB), TB>>>(query, hidden);
    conv_mma_k<128,2><<<512, 256, SM_TOT>>>(pwqB, pA96h, pconv,
                                            pwhB, pB96h, pconv2, 256);
    lindevox_k<128,2><<<2*LBLK, 256, L_TOT>>>(
        query, nullptr, nullptr, pwqlB, wq_lb, pconv, pq,
        hidden, nullptr, nullptr, pwhlB, wh_lb, pconv2, ph, LBLK, 0);

    // --- energy = tanh(sconv([h, q])) ---
    gathervox192_k<<<gs(2LL*G3*24,TB), TB>>>(ph, pq);
    conv_mma_k<192,3><<<256, 256, SM_TOT>>>(pattB, pA192h, pconv,
                                            pattB, pA192h, pconv, 256);
    lindevox_k<192,3><<<LBLK, 256, L_TOT>>>(
        ph, pq, nullptr, pattlB, att_lb, pconv, pe,
        ph, pq, nullptr, pattlB, att_lb, pconv, pe, LBLK, 1);

    // --- attn = sconv(energy), cout=1 ---
    voxdot_k<<<G3/8, 256>>>(pe);
    stencil_k<<<gs(G3,TB), TB>>>();
    attn_k<<<gs(NPTS,TB), TB>>>(pe, v_lw, v_lb);

    // --- out = tanh(sconv([q, attn*h])) ---
    mkq_sc_k<<<gs((long long)G3*36,TB), TB>>>(ph, pattn);
    conv_mma_k<192,3><<<256, 256, SM_TOT>>>(pupdB, pA192h, pconv,
                                            pupdB, pA192h, pconv, 256);
    lindevox_k<192,3><<<LBLK, 256, L_TOT>>>(
        pq, ph, pattn, pupdlB, upd_lb, pconv, out,
        pq, ph, pattn, pupdlB, upd_lb, pconv, out, LBLK, 1);
}

// round 17
// speedup vs baseline: 1.0070x; 1.0070x over previous
#include <cuda_runtime.h>
#include <cuda_fp16.h>
#include <cstdint>
#include <math.h>

#define NPTS 100000
#define CDIM 96
#define GRES 32
#define G3   (GRES*GRES*GRES)
#define PAD  34
#define PP2  (PAD*PAD)
#define PGV  (PP2*PAD)

// ======================= scratch (device globals) ===========================
__device__ int   g_vidx[NPTS];
__device__ int   g_icnt[G3];
__device__ int   g_start[G3+1];
__device__ int   g_pos[G3];
__device__ int   g_sorted[NPTS];
__device__ int   g_nbi[8*NPTS];       // indexed by SORTED slot
__device__ float g_nbw[8*NPTS];       // indexed by SORTED slot
__device__ float g_P[27*G3];          // per-tap dot products (attn stage)
__device__ __half g_conv [G3*CDIM];   // conv outputs in fp16
__device__ __half g_conv2[G3*CDIM];
__device__ float g_vout[G3];
__device__ float g_q[NPTS*CDIM];
__device__ float g_h[NPTS*CDIM];
__device__ float g_energy[NPTS*CDIM];
__device__ float g_attn[NPTS];
// padded fp16 grids (all hi-only; 1-term A everywhere)
__device__ __half g_pA96_hi [PGV*128];   // voxelized query input
__device__ __half g_pB96_hi [PGV*128];   // voxelized hidden input
__device__ __half g_pA192_hi[PGV*192];
// cached voxelized q_out (interior), reused stage3 -> stage5
__device__ __half g_pQ96_hi[PGV*96];
// pre-swizzled fp16 conv weights: [tap*nch+chunk][6144 = 96 rows x 64 ci]
__device__ __half g_wqB [27*2*6144];
__device__ __half g_whB [27*2*6144];
__device__ __half g_attB[27*3*6144];
__device__ __half g_updB[27*3*6144];
// pre-swizzled fp16 linear weights: [chunk][6144]
__device__ __half g_wqlB [2*6144];
__device__ __half g_whlB [2*6144];
__device__ __half g_attlB[3*6144];
__device__ __half g_updlB[3*6144];
__device__ float g_vT[27*CDIM];

// ======================= mma/ldmatrix/cp.async helpers =======================
__device__ __forceinline__ uint32_t smem_u32(const void* p) {
    uint32_t a;
    asm("{ .reg .u64 t; cvta.to.shared.u64 t, %1; cvt.u32.u64 %0, t; }" : "=r"(a) : "l"(p));
    return a;
}
__device__ __forceinline__ void ldsm4(uint32_t* r, uint32_t addr) {
    asm volatile("ldmatrix.sync.aligned.m8n8.x4.shared.b16 {%0,%1,%2,%3}, [%4];"
        : "=r"(r[0]), "=r"(r[1]), "=r"(r[2]), "=r"(r[3]) : "r"(addr));
}
__device__ __forceinline__ void mma16816h(float* c, const uint32_t* a, const uint32_t* b) {
    asm volatile("mma.sync.aligned.m16n8k16.row.col.f32.f16.f16.f32 "
        "{%0,%1,%2,%3}, {%4,%5,%6,%7}, {%8,%9}, {%0,%1,%2,%3};"
        : "+f"(c[0]), "+f"(c[1]), "+f"(c[2]), "+f"(c[3])
        : "r"(a[0]), "r"(a[1]), "r"(a[2]), "r"(a[3]), "r"(b[0]), "r"(b[1]));
}
__device__ __forceinline__ void cpa16(uint32_t dst, const void* src) {
    asm volatile("cp.async.cg.shared.global [%0], [%1], 16;" :: "r"(dst), "l"(src));
}
__device__ __forceinline__ void cpa_commit() { asm volatile("cp.async.commit_group;"); }
__device__ __forceinline__ void cpa_wait0()  { asm volatile("cp.async.wait_group 0;"); }
__device__ __forceinline__ void cpa_wait1()  { asm volatile("cp.async.wait_group 1;"); }

// ======================= sort/index kernels ==================================
__global__ void zeroi_k(int* __restrict__ p, int n) {
    int i = blockIdx.x * blockDim.x + threadIdx.x;
    if (i < n) p[i] = 0;
}

__global__ void vox_k(const float* __restrict__ coords) {
    int p = blockIdx.x * blockDim.x + threadIdx.x;
    if (p >= NPTS) return;
    int vx = min(max((int)floorf(coords[3*p+0]), 0), GRES-1);
    int vy = min(max((int)floorf(coords[3*p+1]), 0), GRES-1);
    int vz = min(max((int)floorf(coords[3*p+2]), 0), GRES-1);
    int flat = (vx*GRES + vy)*GRES + vz;
    g_vidx[p] = flat;
    atomicAdd(&g_icnt[flat], 1);
}

__global__ void __launch_bounds__(1024) scan_k() {
    __shared__ int bs[1024];
    int t = threadIdx.x;
    int base = t * 32;
    int loc[32];
    int s = 0;
    #pragma unroll
    for (int k = 0; k < 32; k++) { loc[k] = s; s += g_icnt[base + k]; }
    bs[t] = s;
    __syncthreads();
    #pragma unroll
    for (int d = 1; d < 1024; d <<= 1) {
        int v = (t >= d) ? bs[t - d] : 0;
        __syncthreads();
        bs[t] += v;
        __syncthreads();
    }
    int off = bs[t] - s;
    #pragma unroll
    for (int k = 0; k < 32; k++) {
        g_start[base + k] = off + loc[k];
        g_pos[base + k]   = off + loc[k];
    }
    if (t == 1023) g_start[G3] = off + s;
}

// fused counting-sort fill + trilinear neighbor precompute (sorted-slot order)
__global__ void filltrilin_k(const float* __restrict__ coords) {
    int p = blockIdx.x * blockDim.x + threadIdx.x;
    if (p >= NPTS) return;
    int s = atomicAdd(&g_pos[g_vidx[p]], 1);
    g_sorted[s] = p;
    float cx = coords[3*p+0], cy = coords[3*p+1], cz = coords[3*p+2];
    float bx = floorf(cx), by = floorf(cy), bz = floorf(cz);
    float fx = cx - bx, fy = cy - by, fz = cz - bz;
    int ix = (int)bx, iy = (int)by, iz = (int)bz;
    #pragma unroll
    for (int j = 0; j < 8; j++) {
        int dx = (j >> 2) & 1, dy = (j >> 1) & 1, dz = j & 1;
        int nx = ix + dx, ny = iy + dy, nz = iz + dz;
        bool valid = (nx >= 0 && nx < GRES && ny >= 0 && ny < GRES && nz >= 0 && nz < GRES);
        int cxc = min(max(nx,0),GRES-1), cyc = min(max(ny,0),GRES-1), czc = min(max(nz,0),GRES-1);
        int flc = (cxc*GRES + cyc)*GRES + czc;
        float w = (dx ? fx : 1.f-fx) * (dy ? fy : 1.f-fy) * (dz ? fz : 1.f-fz);
        if (!valid || g_icnt[flc] == 0) w = 0.f;
        g_nbi[j*NPTS + s] = flc;
        g_nbw[j*NPTS + s] = w;
    }
}

// ======================= fp16 helpers ========================================
__device__ __forceinline__ void f16_store4(float4 acc, __half* dhi, size_t o) {
    __half2 hA = __floats2half2_rn(acc.x, acc.y);
    __half2 hB = __floats2half2_rn(acc.z, acc.w);
    *(__half2*)(dhi + o)     = hA;
    *(__half2*)(dhi + o + 2) = hB;
}

// merged q+h INPUT voxelize (hi only)
__global__ void gathervox_qh_k(const float* __restrict__ q, const float* __restrict__ h) {
    int i = blockIdx.x * blockDim.x + threadIdx.x;
    if (i >= 2 * G3 * 24) return;
    bool sec = (i >= G3 * 24);
    int j = sec ? i - G3 * 24 : i;
    int c4 = j % 24;
    int v  = j / 24;
    int vx = v >> 10, vy = (v >> 5) & 31, vz = v & 31;
    int pv = ((vx + 1) * PAD + (vy + 1)) * PAD + (vz + 1);
    int ci = c4 * 4;
    const float* src = sec ? h : q;

    float4 acc = make_float4(0.f, 0.f, 0.f, 0.f);
    int s0 = g_start[v], s1 = g_start[v+1];
    if (s1 > s0) {
        for (int k = s0; k < s1; k++) {
            int pid = g_sorted[k];
            float4 f = *(const float4*)(src + (size_t)pid * 96 + ci);
            acc.x += f.x; acc.y += f.y; acc.z += f.z; acc.w += f.w;
        }
        float invn = 1.f / (float)(s1 - s0);
        acc.x *= invn; acc.y *= invn; acc.z *= invn; acc.w *= invn;
    }
    f16_store4(acc, sec ? g_pB96_hi : g_pA96_hi, (size_t)pv * 128 + ci);
}

// stage-3 voxelize of OUTPUTS: pA192 = [mean(h_out) | mean(q_out)] + cache q grid
__global__ void gathervox192_k(const float* __restrict__ h, const float* __restrict__ q) {
    int i = blockIdx.x * blockDim.x + threadIdx.x;
    if (i >= 2 * G3 * 24) return;
    bool sec = (i >= G3 * 24);   // sec = q half
    int j = sec ? i - G3 * 24 : i;
    int c4 = j % 24;
    int v  = j / 24;
    int vx = v >> 10, vy = (v >> 5) & 31, vz = v & 31;
    int pv = ((vx + 1) * PAD + (vy + 1)) * PAD + (vz + 1);
    int ci = c4 * 4;
    const float* src = sec ? q : h;

    float4 acc = make_float4(0.f, 0.f, 0.f, 0.f);
    int s0 = g_start[v], s1 = g_start[v+1];
    if (s1 > s0) {
        for (int k = s0; k < s1; k++) {
            int pid = g_sorted[k];
            float4 f = *(const float4*)(src + (size_t)pid * 96 + ci);
            acc.x += f.x; acc.y += f.y; acc.z += f.z; acc.w += f.w;
        }
        float invn = 1.f / (float)(s1 - s0);
        acc.x *= invn; acc.y *= invn; acc.z *= invn; acc.w *= invn;
    }
    if (!sec) {
        f16_store4(acc, g_pA192_hi, (size_t)pv * 192 + ci);
    } else {
        f16_store4(acc, g_pA192_hi, (size_t)pv * 192 + 96 + ci);
        f16_store4(acc, g_pQ96_hi, (size_t)pv * 96 + ci);
    }
}

// stage-5: merged (q-cache copy) + (mean(attn*h) gather)
__global__ void mkq_sc_k(const float* __restrict__ h, const float* __restrict__ scale) {
    const int NCOPY = G3 * 12;
    int i = blockIdx.x * blockDim.x + threadIdx.x;
    if (i < NCOPY) {
        int u = i % 12;
        int v = i / 12;
        int vx = v >> 10, vy = (v >> 5) & 31, vz = v & 31;
        int pv = ((vx + 1) * PAD + (vy + 1)) * PAD + (vz + 1);
        size_t s = (size_t)pv * 96 + u * 8;
        size_t d = (size_t)pv * 192 + u * 8;
        *(uint4*)(g_pA192_hi + d) = *(const uint4*)(g_pQ96_hi + s);
        return;
    }
    int j = i - NCOPY;
    if (j >= G3 * 24) return;
    int c4 = j % 24;
    int v  = j / 24;
    int vx = v >> 10, vy = (v >> 5) & 31, vz = v & 31;
    int pv = ((vx + 1) * PAD + (vy + 1)) * PAD + (vz + 1);
    int ci = c4 * 4;
    float4 acc = make_float4(0.f, 0.f, 0.f, 0.f);
    int s0 = g_start[v], s1 = g_start[v+1];
    if (s1 > s0) {
        for (int k = s0; k < s1; k++) {
            int pid = g_sorted[k];
            float4 f = *(const float4*)(h + (size_t)pid * 96 + ci);
            float m = scale[pid];
            acc.x += f.x * m; acc.y += f.y * m; acc.z += f.z * m; acc.w += f.w * m;
        }
        float invn = 1.f / (float)(s1 - s0);
        acc.x *= invn; acc.y *= invn; acc.z *= invn; acc.w *= invn;
    }
    f16_store4(acc, g_pA192_hi, (size_t)pv * 192 + 96 + ci);
}

// ======================= merged weight prep + grid zero ======================
__device__ __forceinline__ void conv_prep(int i, const float* w, __half* dst,
                                          int CIN, int KPAD, int NCH) {
    int co  = i % 96;
    int r   = i / 96;
    int ci  = r % KPAD;
    int tap = r / KPAD;
    float val = (ci < CIN) ? w[((size_t)co * CIN + ci) * 27 + tap] : 0.f;
    int chunk = ci >> 6;
    int cw = ci & 63;
    uint32_t elem = (uint32_t)co * 64 + (uint32_t)(((cw >> 3) ^ (co & 7)) * 8) + (cw & 7);
    dst[(size_t)(tap * NCH + chunk) * 6144 + elem] = __float2half_rn(val);
}
__device__ __forceinline__ void lin_prep(int i, const float* w, __half* dst, int CIN) {
    int co = i % 96;
    int ci = i / 96;
    float val = (ci < CIN) ? w[(size_t)co * CIN + ci] : 0.f;
    int chunk = ci >> 6;
    int cw = ci & 63;
    uint32_t elem = (uint32_t)co * 64 + (uint32_t)(((cw >> 3) ^ (co & 7)) * 8) + (cw & 7);
    dst[(size_t)chunk * 6144 + elem] = __float2half_rn(val);
}

#define U128 (PGV * 128 / 8)
#define U192 (PGV * 192 / 8)

__global__ void prep_all_k(const float* wq, const float* wh, const float* att,
                           const float* upd, const float* wql, const float* whl,
                           const float* attl, const float* updl, const float* vconv,
                           __half* dwq, __half* dwh, __half* datt, __half* dupd,
                           __half* dwql, __half* dwhl, __half* dattl, __half* dupdl,
                           __half* za, __half* zb, __half* ze) {
    const int C96 = 27*128*96, C192 = 27*192*96, L96 = 128*96, L192 = 192*96;
    long long i = (long long)blockIdx.x * blockDim.x + threadIdx.x;
    uint4 z = make_uint4(0u, 0u, 0u, 0u);
    if (i < U128)            { ((uint4*)za)[i] = z; return; }
    i -= U128;
    if (i < U128)            { ((uint4*)zb)[i] = z; return; }
    i -= U128;
    if (i < U192)            { ((uint4*)ze)[i] = z; return; }
    i -= U192;
    int k = (int)i;
    if (k < C96) { conv_prep(k, wq, dwq, 96, 128, 2); return; }
    k -= C96;
    if (k < C96) { conv_prep(k, wh, dwh, 96, 128, 2); return; }
    k -= C96;
    if (k < C192) { conv_prep(k, att, datt, 192, 192, 3); return; }
    k -= C192;
    if (k < C192) { conv_prep(k, upd, dupd, 192, 192, 3); return; }
    k -= C192;
    if (k < L96) { lin_prep(k, wql, dwql, 96); return; }
    k -= L96;
    if (k < L96) { lin_prep(k, whl, dwhl, 96); return; }
    k -= L96;
    if (k < L192) { lin_prep(k, attl, dattl, 192); return; }
    k -= L192;
    if (k < L192) { lin_prep(k, updl, dupdl, 192); return; }
    k -= L192;
    if (k < 27*96) { int t = k % 27, ci = k / 27; g_vT[t*96 + ci] = vconv[ci*27 + t]; }
}

// ======================= HMMA 3x3x3 conv (slab A hi-only, dual-job) ==========
// R15 structure + B triple-buffer (prefetch depth 2 within each (cc,dx) iter).
#define SM_B0   26112            // A slab: 204 rows * 128B
#define CV_BBUF 12288
#define SM_TOT  62976            // 26112 + 3*12288

template<int KPAD, int NCH>
__global__ void __launch_bounds__(256, 2) conv_mma_k(
    const __half* __restrict__ wBa, const __half* __restrict__ pAhiA,
    __half* __restrict__ outA,
    const __half* __restrict__ wBb, const __half* __restrict__ pAhiB,
    __half* __restrict__ outB,
    int split_blk) {
    extern __shared__ char smem[];
    uint32_t sb = smem_u32(smem);
    int tid = threadIdx.x;
    int warp = tid >> 5, lane = tid & 31;
    int m_off = (warp & 3) * 32;
    int n_off = (warp >> 2) * 48;

    int blk = blockIdx.x;
    bool sec = (blk >= split_blk);
    if (sec) blk -= split_blk;
    const __half* wB   = sec ? wBb   : wBa;
    const __half* pAhi = sec ? pAhiB : pAhiA;
    __half* outp = sec ? outB : outA;

    int x  = blk >> 3;
    int y0 = (blk & 7) * 4;

    float acc[2][6][4];
    #pragma unroll
    for (int mi = 0; mi < 2; mi++)
        #pragma unroll
        for (int nj = 0; nj < 6; nj++)
            #pragma unroll
            for (int e = 0; e < 4; e++) acc[mi][nj][e] = 0.f;

    int a_row_in = (lane & 7) + ((lane >> 3) & 1) * 8;
    int a_khalf  = lane >> 4;
    int b_row_in = (lane & 7) + ((lane >> 3) >> 1) * 8;
    int b_khalf  = (lane >> 3) & 1;

    int rb[2];
    #pragma unroll
    for (int mi = 0; mi < 2; mi++) {
        int m = m_off + mi * 16 + a_row_in;
        rb[mi] = (m >> 5) * 34 + (m & 31);
    }
    int brow[3];
    #pragma unroll
    for (int ni = 0; ni < 3; ni++) brow[ni] = n_off + ni * 16 + b_row_in;

    for (int cc = 0; cc < NCH; cc++) {
        bool shortk = (KPAD == 128 && cc == 1);
        int kmax  = shortk ? 2 : 4;
        int c8max = shortk ? 4 : 8;
        int c8sh  = shortk ? 2 : 3;
        int ahalf = 204 * c8max;

        for (int dx = 0; dx < 3; dx++) {
            __syncthreads();   // all warps done with A slab + B buffers

            // group0 = {A slab, B[0]}; group1 = {B[1]}
            {
                const __half* bs0 = wB + (size_t)((dx * 9) * NCH + cc) * 6144;
                #pragma unroll
                for (int t = tid; t < 768; t += 256)
                    cpa16(sb + SM_B0 + t * 16, bs0 + t * 8);
                size_t pvbase = ((size_t)(x + dx) * PAD + y0) * PAD;
                for (int t = tid; t < ahalf; t += 256) {
                    int r = t >> c8sh, c8 = t & (c8max - 1);
                    const __half* src = pAhi + (pvbase + r) * KPAD + cc * 64 + c8 * 8;
                    cpa16(sb + (uint32_t)r * 128 + ((c8 ^ (r & 7)) << 4), src);
                }
                cpa_commit();
                const __half* bs1 = wB + (size_t)((dx * 9 + 1) * NCH + cc) * 6144;
                #pragma unroll
                for (int t = tid; t < 768; t += 256)
                    cpa16(sb + SM_B0 + CV_BBUF + t * 16, bs1 + t * 8);
                cpa_commit();
            }

            for (int t9 = 0; t9 < 9; t9++) {
                // need A + B[t9] complete; B[t9+1] may stay outstanding
                if (t9 == 8) cpa_wait0(); else cpa_wait1();
                __syncthreads();
                if (t9 + 2 < 9) {   // prefetch B[t9+2] (depth 2)
                    const __half* bs =
                        wB + (size_t)((dx * 9 + t9 + 2) * NCH + cc) * 6144;
                    uint32_t dst = sb + SM_B0 + (uint32_t)((t9 + 2) % 3) * CV_BBUF;
                    #pragma unroll
                    for (int t = tid; t < 768; t += 256)
                        cpa16(dst + t * 16, bs + t * 8);
                    cpa_commit();
                }
                uint32_t bbase = sb + SM_B0 + (uint32_t)(t9 % 3) * CV_BBUF;
                int toff = (t9 / 3) * PAD + (t9 % 3);

                #pragma unroll 4
                for (int kk = 0; kk < kmax; kk++) {
                    uint32_t ah[2][4], bh[3][4];
                    #pragma unroll
                    for (int mi = 0; mi < 2; mi++) {
                        int r = rb[mi] + toff;
                        int kc = kk * 2 + a_khalf;
                        uint32_t off = (uint32_t)r * 128 + (uint32_t)((kc ^ (r & 7)) << 4);
                        ldsm4(ah[mi], sb + off);
                    }
                    #pragma unroll
                    for (int ni = 0; ni < 3; ni++) {
                        int r = brow[ni];
                        int kc = kk * 2 + b_khalf;
                        uint32_t off = (uint32_t)r * 128 + (uint32_t)((kc ^ (r & 7)) << 4);
                        ldsm4(bh[ni], bbase + off);
                    }
                    #pragma unroll
                    for (int mi = 0; mi < 2; mi++) {
                        #pragma unroll
                        for (int nj = 0; nj < 6; nj++) {
                            const uint32_t* bfh = &bh[nj >> 1][(nj & 1) * 2];
                            mma16816h(acc[mi][nj], ah[mi], bfh);
                        }
                    }
                }
            }
        }
    }

    #pragma unroll
    for (int mi = 0; mi < 2; mi++) {
        #pragma unroll
        for (int half = 0; half < 2; half++) {
            int r = m_off + mi * 16 + (lane >> 2) + half * 8;
            int j = r >> 5, z = r & 31;
            size_t vbase = ((size_t)(x * GRES + y0 + j) * GRES + z) * 96;
            #pragma unroll
            for (int nj = 0; nj < 6; nj++) {
                int co = n_off + nj * 8 + 2 * (lane & 3);
                __half2 hv = __floats2half2_rn(acc[mi][nj][half * 2],
                                               acc[mi][nj][half * 2 + 1]);
                *(__half2*)(&outp[vbase + co]) = hv;
            }
        }
    }
}

// ======================= fused linear GEMM + devox epilogue (dual, SORTED) ===
#define L_B0  16384              // A: 128 rows * 128B
#define L_B1  28672
#define L_TOT 40960

template<int KPAD, int NCH>
__global__ void __launch_bounds__(256, 2) lindevox_k(
    const float* __restrict__ x1a, const float* __restrict__ x2a,
    const float* __restrict__ s2a, const __half* __restrict__ wBa,
    const float* __restrict__ biasa, const __half* __restrict__ convA,
    float* __restrict__ outa,
    const float* __restrict__ x1b, const float* __restrict__ x2b,
    const float* __restrict__ s2b, const __half* __restrict__ wBb,
    const float* __restrict__ biasb, const __half* __restrict__ convB,
    float* __restrict__ outb,
    int split_blk, int do_tanh) {
    extern __shared__ char smem[];
    uint32_t sb = smem_u32(smem);
    int tid = threadIdx.x;
    int warp = tid >> 5, lane = tid & 31;
    int m_off = (warp & 3) * 32;
    int n_off = (warp >> 2) * 48;

    int blk = blockIdx.x;
    bool sec = (blk >= split_blk);
    if (sec) blk -= split_blk;
    const float* x1 = sec ? x1b : x1a;
    const float* x2 = sec ? x2b : x2a;
    const float* scale2 = sec ? s2b : s2a;
    const __half* wB = sec ? wBb : wBa;
    const float* bias = sec ? biasb : biasa;
    const __half* convsrc = sec ? convB : convA;
    float* out = sec ? outb : outa;
    int pbase = blk * 128;           // SORTED slot base

    float acc[2][6][4];
    #pragma unroll
    for (int mi = 0; mi < 2; mi++)
        #pragma unroll
        for (int nj = 0; nj < 6; nj++)
            #pragma unroll
            for (int e = 0; e < 4; e++) acc[mi][nj][e] = 0.f;

    int a_row_in = (lane & 7) + ((lane >> 3) & 1) * 8;
    int a_khalf  = lane >> 4;
    int b_row_in = (lane & 7) + ((lane >> 3) >> 1) * 8;
    int b_khalf  = (lane >> 3) & 1;
    int brow[3];
    #pragma unroll
    for (int ni = 0; ni < 3; ni++) brow[ni] = n_off + ni * 16 + b_row_in;

    #pragma unroll
    for (int t = tid; t < 768; t += 256)
        cpa16(sb + L_B0 + t * 16, wB + t * 8);
    cpa_commit();

    for (int ch = 0; ch < NCH; ch++) {
        if (ch) __syncthreads();
        bool shortk = (KPAD == 128 && ch == 1);
        int kmax  = shortk ? 2 : 4;
        int c8max = shortk ? 4 : 8;
        int c8sh  = shortk ? 2 : 3;

        for (int gidx = tid; gidx < 128 * c8max; gidx += 256) {
            int r = gidx >> c8sh, c8 = gidx & (c8max - 1);
            int slot = pbase + r;
            int colbase = ch * 64 + c8 * 8;
            float v[8];
            bool have = (slot < NPTS) && (colbase < ((KPAD == 128) ? 96 : 192));
            if (have) {
                int p = g_sorted[slot];
                const float* srcp;
                float m = 1.f;
                if (colbase < 96) srcp = x1 + (size_t)p * 96 + colbase;
                else {
                    srcp = x2 + (size_t)p * 96 + (colbase - 96);
                    if (scale2) m = scale2[p];
                }
                float4 aa = *(const float4*)srcp;
                float4 bb = *(const float4*)(srcp + 4);
                v[0]=aa.x*m; v[1]=aa.y*m; v[2]=aa.z*m; v[3]=aa.w*m;
                v[4]=bb.x*m; v[5]=bb.y*m; v[6]=bb.z*m; v[7]=bb.w*m;
            } else {
                #pragma unroll
                for (int e = 0; e < 8; e++) v[e] = 0.f;
            }
            uint4 hv;
            uint32_t* hp = (uint32_t*)&hv;
            #pragma unroll
            for (int e = 0; e < 4; e++) {
                __half2 hh = __floats2half2_rn(v[2*e], v[2*e+1]);
                hp[e] = *(uint32_t*)&hh;
            }
            uint32_t addr = (uint32_t)r * 128 + (uint32_t)((c8 ^ (r & 7)) << 4);
            *(uint4*)(smem + addr) = hv;
        }
        if (ch + 1 < NCH) {
            const __half* bs = wB + (size_t)(ch + 1) * 6144;
            uint32_t dst = sb + ((ch & 1) ? L_B0 : L_B1);
            #pragma unroll
            for (int t = tid; t < 768; t += 256)
                cpa16(dst + t * 16, bs + t * 8);
            cpa_commit();
            cpa_wait1();
        } else {
            cpa_wait0();
        }
        __syncthreads();

        uint32_t bbase = sb + ((ch & 1) ? L_B1 : L_B0);
        #pragma unroll 4
        for (int kk = 0; kk < kmax; kk++) {
            uint32_t ah[2][4], bh[3][4];
            #pragma unroll
            for (int mi = 0; mi < 2; mi++) {
                int r = m_off + mi * 16 + a_row_in;
                int kc = kk * 2 + a_khalf;
                uint32_t off = (uint32_t)r * 128 + (uint32_t)((kc ^ (r & 7)) << 4);
                ldsm4(ah[mi], sb + off);
            }
            #pragma unroll
            for (int ni = 0; ni < 3; ni++) {
                int r = brow[ni];
                int kc = kk * 2 + b_khalf;
                uint32_t off = (uint32_t)r * 128 + (uint32_t)((kc ^ (r & 7)) << 4);
                ldsm4(bh[ni], bbase + off);
            }
            #pragma unroll
            for (int mi = 0; mi < 2; mi++) {
                #pragma unroll
                for (int nj = 0; nj < 6; nj++) {
                    const uint32_t* bfh = &bh[nj >> 1][(nj & 1) * 2];
                    mma16816h(acc[mi][nj], ah[mi], bfh);
                }
            }
        }
    }

    // ---- epilogue: devox gather (fp16 conv, sorted slots) + bias + tanh ----
    #pragma unroll
    for (int mi = 0; mi < 2; mi++) {
        #pragma unroll
        for (int half = 0; half < 2; half++) {
            int r = m_off + mi * 16 + (lane >> 2) + half * 8;
            int slot = pbase + r;
            if (slot >= NPTS) continue;
            int p = g_sorted[slot];
            #pragma unroll
            for (int j = 0; j < 8; j++) {
                float w = g_nbw[j*NPTS + slot];
                if (w != 0.f) {
                    const __half* gp = convsrc + (size_t)g_nbi[j*NPTS + slot] * 96;
                    #pragma unroll
                    for (int nj = 0; nj < 6; nj++) {
                        int co = n_off + nj * 8 + 2 * (lane & 3);
                        float2 gg = __half22float2(*(const __half2*)(gp + co));
                        acc[mi][nj][half*2]   += w * gg.x;
                        acc[mi][nj][half*2+1] += w * gg.y;
                    }
                }
            }
            #pragma unroll
            for (int nj = 0; nj < 6; nj++) {
                int co = n_off + nj * 8 + 2 * (lane & 3);
                float2 bb = *(const float2*)(bias + co);
                float vx = acc[mi][nj][half*2]   + bb.x;
                float vy = acc[mi][nj][half*2+1] + bb.y;
                if (do_tanh) { vx = tanhf(vx); vy = tanhf(vy); }
                *(float2*)(out + (size_t)p * 96 + co) = make_float2(vx, vy);
            }
        }
    }
}

// ======================= attn stage ==========================================
__global__ void __launch_bounds__(256) voxdot_k(const float* __restrict__ src) {
    __shared__ float ws[27*96];
    int tid = threadIdx.x;
    for (int i = tid; i < 27*96; i += 256) ws[i] = g_vT[i];
    __syncthreads();
    int wid = tid >> 5, lane = tid & 31;
    int v = blockIdx.x * 8 + wid;
    if (v >= G3) return;
    int s0 = g_start[v], s1 = g_start[v+1];
    float a0 = 0.f, a1 = 0.f, a2 = 0.f;
    for (int k = s0; k < s1; k++) {
        const float* r = src + (size_t)g_sorted[k] * 96;
        a0 += r[lane]; a1 += r[lane+32]; a2 += r[lane+64];
    }
    if (s1 > s0) {
        float invn = 1.f / (float)(s1 - s0);
        a0 *= invn; a1 *= invn; a2 *= invn;
    }
    #pragma unroll 9
    for (int t = 0; t < 27; t++) {
        float s = a0*ws[t*96+lane] + a1*ws[t*96+lane+32] + a2*ws[t*96+lane+64];
        s += __shfl_xor_sync(0xFFFFFFFF, s, 16);
        s += __shfl_xor_sync(0xFFFFFFFF, s, 8);
        s += __shfl_xor_sync(0xFFFFFFFF, s, 4);
        s += __shfl_xor_sync(0xFFFFFFFF, s, 2);
        s += __shfl_xor_sync(0xFFFFFFFF, s, 1);
        if (lane == 0) g_P[t*G3 + v] = s;
    }
}

__global__ void stencil_k() {
    int v = blockIdx.x * blockDim.x + threadIdx.x;
    if (v >= G3) return;
    int px = v >> 10, py = (v >> 5) & 31, pz = v & 31;
    float acc = 0.f;
    #pragma unroll
    for (int t = 0; t < 27; t++) {
        int kx = t / 9, ky = (t / 3) % 3, kz = t % 3;
        int nx = px + kx - 1, ny = py + ky - 1, nz = pz + kz - 1;
        if ((unsigned)nx < GRES && (unsigned)ny < GRES && (unsigned)nz < GRES)
            acc += g_P[t*G3 + ((nx<<5) + ny)*32 + nz];
    }
    g_vout[v] = acc;
}

__global__ void attn_k(const float* __restrict__ energy,
                       const float* __restrict__ v_lw, const float* __restrict__ v_lb) {
    int s = blockIdx.x * blockDim.x + threadIdx.x;
    if (s >= NPTS) return;
    int p = g_sorted[s];
    float acc = v_lb[0];
    #pragma unroll
    for (int j = 0; j < 8; j++) {
        float w = g_nbw[j*NPTS + s];
        if (w != 0.f) acc += w * g_vout[g_nbi[j*NPTS + s]];
    }
    const float4* er4 = (const float4*)(energy + (size_t)p * CDIM);
    const float4* vw4 = (const float4*)v_lw;
    #pragma unroll 6
    for (int cb = 0; cb < 24; cb++) {
        float4 e = er4[cb], w = vw4[cb];
        acc += e.x*w.x + e.y*w.y + e.z*w.z + e.w*w.w;
    }
    g_attn[p] = acc;
}

// ======================= host orchestration =================================
extern "C" void kernel_launch(void* const* d_in, const int* in_sizes, int n_in,
                              void* d_out, int out_size) {
    const float* hidden   = (const float*)d_in[0];
    const float* query    = (const float*)d_in[1];
    const float* coords   = (const float*)d_in[2];
    const float* wq_conv  = (const float*)d_in[3];
    const float* wq_lw    = (const float*)d_in[4];
    const float* wq_lb    = (const float*)d_in[5];
    const float* wh_conv  = (const float*)d_in[6];
    const float* wh_lw    = (const float*)d_in[7];
    const float* wh_lb    = (const float*)d_in[8];
    const float* att_conv = (const float*)d_in[9];
    const float* att_lw   = (const float*)d_in[10];
    const float* att_lb   = (const float*)d_in[11];
    const float* v_conv   = (const float*)d_in[12];
    const float* v_lw     = (const float*)d_in[13];
    const float* v_lb     = (const float*)d_in[14];
    const float* upd_conv = (const float*)d_in[15];
    const float* upd_lw   = (const float*)d_in[16];
    const float* upd_lb   = (const float*)d_in[17];
    float* out = (float*)d_out;

    int *picnt;
    float *pq, *ph, *pe, *pattn;
    __half *pconv, *pconv2;
    __half *pwqB, *pwhB, *pattB, *pupdB;
    __half *pwqlB, *pwhlB, *pattlB, *pupdlB;
    __half *pA96h, *pB96h, *pA192h;
    cudaGetSymbolAddress((void**)&picnt,  g_icnt);
    cudaGetSymbolAddress((void**)&pq,     g_q);
    cudaGetSymbolAddress((void**)&ph,     g_h);
    cudaGetSymbolAddress((void**)&pe,     g_energy);
    cudaGetSymbolAddress((void**)&pattn,  g_attn);
    cudaGetSymbolAddress((void**)&pconv,  g_conv);
    cudaGetSymbolAddress((void**)&pconv2, g_conv2);
    cudaGetSymbolAddress((void**)&pwqB,   g_wqB);
    cudaGetSymbolAddress((void**)&pwhB,   g_whB);
    cudaGetSymbolAddress((void**)&pattB,  g_attB);
    cudaGetSymbolAddress((void**)&pupdB,  g_updB);
    cudaGetSymbolAddress((void**)&pwqlB,  g_wqlB);
    cudaGetSymbolAddress((void**)&pwhlB,  g_whlB);
    cudaGetSymbolAddress((void**)&pattlB, g_attlB);
    cudaGetSymbolAddress((void**)&pupdlB, g_updlB);
    cudaGetSymbolAddress((void**)&pA96h,  g_pA96_hi);
    cudaGetSymbolAddress((void**)&pB96h,  g_pB96_hi);
    cudaGetSymbolAddress((void**)&pA192h, g_pA192_hi);

    cudaFuncSetAttribute(conv_mma_k<128,2>, cudaFuncAttributeMaxDynamicSharedMemorySize, SM_TOT);
    cudaFuncSetAttribute(conv_mma_k<192,3>, cudaFuncAttributeMaxDynamicSharedMemorySize, SM_TOT);
    cudaFuncSetAttribute(lindevox_k<128,2>, cudaFuncAttributeMaxDynamicSharedMemorySize, L_TOT);
    cudaFuncSetAttribute(lindevox_k<192,3>, cudaFuncAttributeMaxDynamicSharedMemorySize, L_TOT);

    const int TB = 256;
    auto gs = [](long long n, int tb){ return (int)((n + tb - 1) / tb); };
    const int LBLK = (NPTS + 127) / 128;   // 782
    const long long ZN = 2LL*U128 + 1LL*U192;
    const long long PREP_N = ZN + 2LL*27*128*96 + 2LL*27*192*96
                           + 2LL*128*96 + 2LL*192*96 + 27*96;

    // --- shared precompute ---
    zeroi_k<<<gs(G3,TB), TB>>>(picnt, G3);
    vox_k<<<gs(NPTS,TB), TB>>>(coords);
    scan_k<<<1, 1024>>>();
    filltrilin_k<<<gs(NPTS,TB), TB>>>(coords);
    prep_all_k<<<gs(PREP_N,TB), TB>>>(wq_conv, wh_conv, att_conv, upd_conv,
                                      wq_lw, wh_lw, att_lw, upd_lw, v_conv,
                                      pwqB, pwhB, pattB, pupdB,
                                      pwqlB, pwhlB, pattlB, pupdlB,
                                      pA96h, pB96h, pA192h);

    // --- merged sconv q + sconv h ---
    gathervox_qh_k<<<gs(2LL*G3*24,TB), TB>>>(query, hidden);
    conv_mma_k<128,2><<<512, 256, SM_TOT>>>(pwqB, pA96h, pconv,
                                            pwhB, pB96h, pconv2, 256);
    lindevox_k<128,2><<<2*LBLK, 256, L_TOT>>>(
        query, nullptr, nullptr, pwqlB, wq_lb, pconv, pq,
        hidden, nullptr, nullptr, pwhlB, wh_lb, pconv2, ph, LBLK, 0);

    // --- energy = tanh(sconv([h, q])) ---
    gathervox192_k<<<gs(2LL*G3*24,TB), TB>>>(ph, pq);
    conv_mma_k<192,3><<<256, 256, SM_TOT>>>(pattB, pA192h, pconv,
                                            pattB, pA192h, pconv, 256);
    lindevox_k<192,3><<<LBLK, 256, L_TOT>>>(
        ph, pq, nullptr, pattlB, att_lb, pconv, pe,
        ph, pq, nullptr, pattlB, att_lb, pconv, pe, LBLK, 1);

    // --- attn = sconv(energy), cout=1 ---
    voxdot_k<<<G3/8, 256>>>(pe);
    stencil_k<<<gs(G3,TB), TB>>>();
    attn_k<<<gs(NPTS,TB), TB>>>(pe, v_lw, v_lb);

    // --- out = tanh(sconv([q, attn*h])) ---
    mkq_sc_k<<<gs((long long)G3*36,TB), TB>>>(ph, pattn);
    conv_mma_k<192,3><<<256, 256, SM_TOT>>>(pupdB, pA192h, pconv,
                                            pupdB, pA192h, pconv, 256);
    lindevox_k<192,3><<<LBLK, 256, L_TOT>>>(
        pq, ph, pattn, pupdlB, upd_lb, pconv, out,
        pq, ph, pattn, pupdlB, upd_lb, pconv, out, LBLK, 1);
}